// round 16
// baseline (speedup 1.0000x reference)
#include <cuda_runtime.h>
#include <cuda_bf16.h>
#include <cuda_fp16.h>
#include <cstdint>

#define NROWS 8192
#define DIM   128
#define TILE  128
#define NTILES (NROWS / TILE)             // 64
#define NUNITS 2080
#define GRIDN  444                        // 3 CTAs/SM x 148
#define NR_PER_CTA 20                     // 444*20 = 8880 >= 8192

// sqrt(log2(e)/0.1) — baked into both operands so acc = sim*log2(e)/T
#define ROOT_SCALE 3.79828255588053f

// dynamic smem: A0 16K | A1 16K | B0 16K | B1 16K
#define SM_TOTAL 65536

__device__ uint8_t g_f8[NROWS * DIM];    // normalized * ROOT_SCALE, e4m3
__device__ float g_pos[NROWS];
__device__ float g_all[NROWS];
__device__ unsigned g_bar[3];            // spin barriers (self-cleaning)
__device__ float g_rsum;
__device__ int   g_rnv;
__device__ int   g_rnfg;

// ============================ PTX helpers ============================
__device__ __forceinline__ uint32_t smem_u32(const void* p) {
    uint32_t a;
    asm("{ .reg .u64 t; cvta.to.shared.u64 t, %1; cvt.u32.u64 %0, t; }"
        : "=r"(a) : "l"(p));
    return a;
}
__device__ __forceinline__ float fast_ex2(float x) {
    float r; asm("ex2.approx.f32 %0, %1;" : "=f"(r) : "f"(x)); return r;
}
#define CP_ASYNC16(dst, src) \
    asm volatile("cp.async.cg.shared.global [%0], [%1], 16;" \
                 :: "r"(dst), "l"(src) : "memory")
#define CP_COMMIT() asm volatile("cp.async.commit_group;" ::: "memory")
#define CP_WAIT0()  asm volatile("cp.async.wait_group 0;" ::: "memory")
#define CP_WAIT1()  asm volatile("cp.async.wait_group 1;" ::: "memory")

__device__ __forceinline__ void ldsm4(uint32_t* r, uint32_t addr) {
    asm volatile("ldmatrix.sync.aligned.m8n8.x4.shared.b16 {%0,%1,%2,%3}, [%4];"
                 : "=r"(r[0]), "=r"(r[1]), "=r"(r[2]), "=r"(r[3]) : "r"(addr));
}
// fp8 e4m3 MMA, K=32, f16 accumulate
__device__ __forceinline__ void mma16832h(uint32_t* d, const uint32_t* a,
                                          uint32_t b0, uint32_t b1) {
    asm volatile(
        "mma.sync.aligned.m16n8k32.row.col.f16.e4m3.e4m3.f16 "
        "{%0,%1}, {%2,%3,%4,%5}, {%6,%7}, {%0,%1};"
        : "+r"(d[0]), "+r"(d[1])
        : "r"(a[0]), "r"(a[1]), "r"(a[2]), "r"(a[3]), "r"(b0), "r"(b1));
}

// device-wide barrier: all 444 CTAs resident (guaranteed by launch_bounds) -> safe.
__device__ __forceinline__ void gsync(int i) {
    __syncthreads();
    if (threadIdx.x == 0) {
        __threadfence();
        atomicAdd(&g_bar[i], 1u);
        while (*((volatile unsigned*)&g_bar[i]) < GRIDN) { }
        __threadfence();
    }
    __syncthreads();
}

// Load a 128-row x 128-byte tile, k-group-major: addr = (g*128 + row)*16.
__device__ __forceinline__ void load_tile(uint32_t dst, int rowbase, int tid) {
#pragma unroll
    for (int it = 0; it < 4; ++it) {
        int id = it * 256 + tid;          // 0..1023
        int g = id >> 7, r = id & 127;
        const uint8_t* src = g_f8 + (size_t)(rowbase + r) * DIM + g * 16;
        CP_ASYNC16(dst + (uint32_t)id * 16u, src);
    }
}

// It-major flat enumeration: It<32 own s=0..32 (33 units), It>=32 own s=0..31.
__device__ __forceinline__ void decode_unit(int p, int& It, int& s) {
    if (p < 1056) { It = p / 33; s = p - It * 33; }
    else          { int q = p - 1056; It = 32 + (q >> 5); s = q & 31; }
}

__device__ __forceinline__ uint32_t pack_e4m3x4(float x0, float x1, float x2, float x3) {
    uint16_t p01, p23;
    asm("cvt.rn.satfinite.e4m3x2.f32 %0, %1, %2;" : "=h"(p01) : "f"(x1), "f"(x0));
    asm("cvt.rn.satfinite.e4m3x2.f32 %0, %1, %2;" : "=h"(p23) : "f"(x3), "f"(x2));
    return (uint32_t)p01 | ((uint32_t)p23 << 16);
}
__device__ __forceinline__ __half2 h2_of(uint32_t u) {
    return *reinterpret_cast<const __half2*>(&u);
}
__device__ __forceinline__ uint32_t u_of(__half2 h) {
    return *reinterpret_cast<const uint32_t*>(&h);
}

// ============================ epilogues ============================
// Diagonal tile: float path (64/2080 tiles only), loads its own int labels.
__device__ __forceinline__ void epi_diag(
    const uint32_t c[4][4][2], const int* __restrict__ labels, int jb, int ibase,
    int m0, int n0, int lane,
    float* all_lo, float* all_hi, float* pos_lo, float* pos_hi)
{
    int li_lo[4], li_hi[4];
#pragma unroll
    for (int m = 0; m < 4; ++m) {
        li_lo[m] = __ldg(&labels[ibase + m0 + m * 16 + (lane >> 2)]);
        li_hi[m] = __ldg(&labels[ibase + m0 + m * 16 + (lane >> 2) + 8]);
    }
#pragma unroll
    for (int n = 0; n < 4; ++n) {
        const int cl  = n0 + n * 8 + (lane & 3) * 2;
        const int lj0 = __ldg(&labels[jb + cl]);
        const int lj1 = __ldg(&labels[jb + cl + 1]);
        const int j0  = jb + cl;
        const int j1  = j0 + 1;
#pragma unroll
        for (int m = 0; m < 4; ++m) {
            const int i_lo = ibase + m0 + m * 16 + (lane >> 2);
            const int i_hi = i_lo + 8;
            const float2 p01 = __half22float2(h2_of(c[m][n][0]));
            const float2 p23 = __half22float2(h2_of(c[m][n][1]));
            float e0 = fast_ex2(p01.x);
            float e1 = fast_ex2(p01.y);
            float e2 = fast_ex2(p23.x);
            float e3 = fast_ex2(p23.y);
            e0 = ((lj0 >= 0) && (j0 != i_lo)) ? e0 : 0.0f;
            e1 = ((lj1 >= 0) && (j1 != i_lo)) ? e1 : 0.0f;
            e2 = ((lj0 >= 0) && (j0 != i_hi)) ? e2 : 0.0f;
            e3 = ((lj1 >= 0) && (j1 != i_hi)) ? e3 : 0.0f;
            all_lo[m] += e0 + e1;
            all_hi[m] += e2 + e3;
            pos_lo[m] += ((lj0 == li_lo[m]) ? e0 : 0.0f) + ((lj1 == li_lo[m]) ? e1 : 0.0f);
            pos_hi[m] += ((lj0 == li_hi[m]) ? e2 : 0.0f) + ((lj1 == li_hi[m]) ? e3 : 0.0f);
        }
    }
}

// Off-diagonal tile: f16x2-SIMD path; fg_i masks recomputed from rlo/rhi (reg diet).
__device__ __forceinline__ void epi_offdiag_h2(
    const uint32_t c[4][4][2], const int* __restrict__ labels, int jb,
    int n0, int lane,
    const __half2* rlo, const __half2* rhi,
    float* all_lo, float* all_hi, float* pos_lo, float* pos_hi)
{
    const __half2 hz = __float2half2_rn(0.0f);
    __half2 colh[4], fgm[4], hca[4], hcp[4];
#pragma unroll
    for (int n = 0; n < 4; ++n) {
        const int cl = n0 + n * 8 + (lane & 3) * 2;
        const int lj0 = __ldg(&labels[jb + cl]);
        const int lj1 = __ldg(&labels[jb + cl + 1]);
        colh[n] = __halves2half2(__int2half_rn(lj0), __int2half_rn(lj1));
        fgm[n]  = __hge2(colh[n], hz);      // {fg_j0, fg_j1}
        hca[n] = hz; hcp[n] = hz;
    }
#pragma unroll
    for (int m = 0; m < 4; ++m) {
        const __half2 glo = __hge2(rlo[m], hz);   // fg_i masks, on the fly
        const __half2 ghi = __hge2(rhi[m], hz);
        __half2 sal = hz, sah = hz, spl = hz, sph = hz;
#pragma unroll
        for (int n = 0; n < 4; ++n) {
            const __half2 e0 = h2exp2(h2_of(c[m][n][0]));   // row i_lo, 2 cols
            const __half2 e1 = h2exp2(h2_of(c[m][n][1]));   // row i_hi, 2 cols
            const __half2 eq0 = __heq2(colh[n], rlo[m]);    // eq => both fg
            const __half2 eq1 = __heq2(colh[n], rhi[m]);
            const __half2 pe0 = __hmul2(e0, eq0);
            const __half2 pe1 = __hmul2(e1, eq1);
            sal = __hadd2(sal, __hmul2(e0, fgm[n]));        // row all (mask fg_j)
            sah = __hadd2(sah, __hmul2(e1, fgm[n]));
            spl = __hadd2(spl, pe0);                        // row pos
            sph = __hadd2(sph, pe1);
            hca[n] = __hadd2(hca[n], __hadd2(__hmul2(e0, glo),   // col all (mask fg_i)
                                             __hmul2(e1, ghi)));
            hcp[n] = __hadd2(hcp[n], __hadd2(pe0, pe1));    // col pos
        }
        float2 f;
        f = __half22float2(sal); all_lo[m] += f.x + f.y;
        f = __half22float2(sah); all_hi[m] += f.x + f.y;
        f = __half22float2(spl); pos_lo[m] += f.x + f.y;
        f = __half22float2(sph); pos_hi[m] += f.x + f.y;
    }
    // column partials: reduce in PACKED half2 across the 8 lanes sharing each column
#pragma unroll
    for (int n = 0; n < 4; ++n) {
        uint32_t ua = u_of(hca[n]);
        uint32_t up = u_of(hcp[n]);
#pragma unroll
        for (int o = 4; o <= 16; o <<= 1) {
            ua = u_of(__hadd2(h2_of(ua), h2_of(__shfl_xor_sync(0xffffffffu, ua, o))));
            up = u_of(__hadd2(h2_of(up), h2_of(__shfl_xor_sync(0xffffffffu, up, o))));
        }
        hca[n] = h2_of(ua);
        hcp[n] = h2_of(up);
    }
    if (lane < 4) {
#pragma unroll
        for (int n = 0; n < 4; ++n) {
            const int j0 = jb + n0 + n * 8 + lane * 2;
            const float2 a = __half22float2(hca[n]);
            const float2 p = __half22float2(hcp[n]);
            atomicAdd(&g_all[j0],     a.x);
            atomicAdd(&g_pos[j0],     p.x);
            atomicAdd(&g_all[j0 + 1], a.y);
            atomicAdd(&g_pos[j0 + 1], p.y);
        }
    }
}

__device__ __forceinline__ void flush_rows(
    int ibase, int m0, int lane,
    float* all_lo, float* all_hi, float* pos_lo, float* pos_hi)
{
#pragma unroll
    for (int m = 0; m < 4; ++m) {
#pragma unroll
        for (int o = 1; o <= 2; o <<= 1) {
            all_lo[m] += __shfl_xor_sync(0xffffffffu, all_lo[m], o);
            all_hi[m] += __shfl_xor_sync(0xffffffffu, all_hi[m], o);
            pos_lo[m] += __shfl_xor_sync(0xffffffffu, pos_lo[m], o);
            pos_hi[m] += __shfl_xor_sync(0xffffffffu, pos_hi[m], o);
        }
    }
    if ((lane & 3) == 0) {
#pragma unroll
        for (int m = 0; m < 4; ++m) {
            const int rr = ibase + m0 + m * 16 + (lane >> 2);
            atomicAdd(&g_all[rr],     all_lo[m]);
            atomicAdd(&g_pos[rr],     pos_lo[m]);
            atomicAdd(&g_all[rr + 8], all_hi[m]);
            atomicAdd(&g_pos[rr + 8], pos_hi[m]);
        }
    }
}

// ============================ Fused persistent kernel ============================
__global__ __launch_bounds__(256, 3) void cpe_fused_kernel(
    const float* __restrict__ feat, const int* __restrict__ labels,
    float* __restrict__ out)
{
    extern __shared__ char smem[];
    const uint32_t sb = smem_u32(smem);
    __shared__ float s_rs[8];
    __shared__ int   s_rv[8], s_rf[8];

    const int tid  = threadIdx.x;
    const int lane = tid & 31;
    const int wid  = tid >> 5;

    // ---------------- Phase 0: normalize -> e4m3, zero accumulators ----------------
    {
        const int base = blockIdx.x * NR_PER_CTA;   // 20 rows = 10 pairs
        for (int pi = wid; pi < NR_PER_CTA / 2; pi += 8) {
            const int row0 = base + 2 * pi;
            if (row0 < NROWS) {
                float4 v0 = ((const float4*)(feat + (size_t)row0 * DIM))[lane];
                float4 v1 = ((const float4*)(feat + (size_t)(row0 + 1) * DIM))[lane];
                float s0 = v0.x * v0.x + v0.y * v0.y + v0.z * v0.z + v0.w * v0.w;
                float s1 = v1.x * v1.x + v1.y * v1.y + v1.z * v1.z + v1.w * v1.w;
#pragma unroll
                for (int o = 16; o > 0; o >>= 1) {
                    s0 += __shfl_xor_sync(0xffffffffu, s0, o);
                    s1 += __shfl_xor_sync(0xffffffffu, s1, o);
                }
                float i0 = rsqrtf(fmaxf(s0, 1e-24f)) * ROOT_SCALE;
                float i1 = rsqrtf(fmaxf(s1, 1e-24f)) * ROOT_SCALE;
                ((uint32_t*)(g_f8 + (size_t)row0 * DIM))[lane] =
                    pack_e4m3x4(v0.x * i0, v0.y * i0, v0.z * i0, v0.w * i0);
                ((uint32_t*)(g_f8 + (size_t)(row0 + 1) * DIM))[lane] =
                    pack_e4m3x4(v1.x * i1, v1.y * i1, v1.z * i1, v1.w * i1);
                if (lane == 0) {
                    g_pos[row0] = 0.0f; g_all[row0] = 0.0f;
                    g_pos[row0 + 1] = 0.0f; g_all[row0 + 1] = 0.0f;
                }
            }
        }
    }
    gsync(0);

    // ---------------- Phase 1: symmetric FP8 GEMM + fused exp-sum epilogue ----------------
    {
        const int m0 = (wid >> 2) * 64;
        const int n0 = (wid & 3) * 32;
        const __half2 hz = __float2half2_rn(0.0f);

        const int matid = lane >> 3, r = lane & 7;
        uint32_t a_off[4];
#pragma unroll
        for (int m = 0; m < 4; ++m)
            a_off[m] = (uint32_t)((matid >> 1) * 2048 +
                       (m0 + m * 16 + ((matid & 1) << 3) + r) * 16);
        const uint32_t b_off0 = (uint32_t)((matid & 1) * 2048 + (n0 +      ((matid >> 1) << 3) + r) * 16);
        const uint32_t b_off1 = (uint32_t)((matid & 1) * 2048 + (n0 + 16 + ((matid >> 1) << 3) + r) * 16);

        // contiguous chunk of the flat unit list: 2080 = 304*5 + 140*4
        const int b = blockIdx.x;
        const int p0  = b * 4 + min(b, 304);
        const int cnt = 4 + (b < 304 ? 1 : 0);

        int It0, s0;
        decode_unit(p0, It0, s0);
        // end of It0's segment in the flat enumeration
        const int segend = (It0 < 32) ? (It0 + 1) * 33 : 1056 + (It0 - 31) * 32;
        const int tb  = min(cnt, segend - p0);   // units in first segment
        const int It1 = It0 + 1;                 // second segment (if tb < cnt)

        // initial loads: group1 = A0 (+A1) + B(0);  group2 = B(1)
        load_tile(sb, It0 * TILE, tid);
        if (tb < cnt) load_tile(sb + 16384u, It1 * TILE, tid);
        load_tile(sb + 32768u, ((It0 + s0) & (NTILES - 1)) * TILE, tid);
        CP_COMMIT();
        {
            int Itt, st; decode_unit(p0 + 1, Itt, st);
            load_tile(sb + 49152u, ((Itt + st) & (NTILES - 1)) * TILE, tid);
        }
        CP_COMMIT();

        // row labels for first segment
        int ibase = It0 * TILE;
        __half2 rlo[4], rhi[4];
#pragma unroll
        for (int m = 0; m < 4; ++m) {
            const int llo = __ldg(&labels[ibase + m0 + m * 16 + (lane >> 2)]);
            const int lhi = __ldg(&labels[ibase + m0 + m * 16 + (lane >> 2) + 8]);
            rlo[m] = __half2half2(__int2half_rn(llo));
            rhi[m] = __half2half2(__int2half_rn(lhi));
        }
        float all_lo[4] = {0,0,0,0}, all_hi[4] = {0,0,0,0};
        float pos_lo[4] = {0,0,0,0}, pos_hi[4] = {0,0,0,0};

        CP_WAIT1();            // group1 (A tiles + B0) complete; B1 may be in flight
        __syncthreads();

        for (int t = 0; t < cnt; ++t) {
            const uint32_t SA = sb + ((t < tb) ? 0u : 16384u);
            const uint32_t SB = sb + 32768u + (uint32_t)(t & 1) * 16384u;

            // -------- mainloop: 16 fp8 MMAs x 4 k-steps --------
            uint32_t c[4][4][2];
#pragma unroll
            for (int m = 0; m < 4; ++m)
#pragma unroll
                for (int n = 0; n < 4; ++n) { c[m][n][0] = 0u; c[m][n][1] = 0u; }

#pragma unroll
            for (int ks = 0; ks < 4; ++ks) {
                const uint32_t kadv = (uint32_t)ks * 4096u;
                uint32_t af[4][4];
#pragma unroll
                for (int m = 0; m < 4; ++m) ldsm4(af[m], SA + a_off[m] + kadv);
                uint32_t bf0[4], bf1[4];
                ldsm4(bf0, SB + b_off0 + kadv);
                ldsm4(bf1, SB + b_off1 + kadv);
#pragma unroll
                for (int m = 0; m < 4; ++m) {
                    mma16832h(c[m][0], af[m], bf0[0], bf0[1]);
                    mma16832h(c[m][1], af[m], bf0[2], bf0[3]);
                    mma16832h(c[m][2], af[m], bf1[0], bf1[1]);
                    mma16832h(c[m][3], af[m], bf1[2], bf1[3]);
                }
            }

            // -------- barrier right after uniform mainloop; then prefetch t+2 --------
            if (t + 1 < cnt) {
                CP_WAIT0();          // B(t+1) data arrived (only group outstanding)
                __syncthreads();     // all warps done reading SB -> safe to overwrite
                if (t + 2 < cnt) {
                    int It2, s2; decode_unit(p0 + t + 2, It2, s2);
                    load_tile(SB, ((It2 + s2) & (NTILES - 1)) * TILE, tid);
                    CP_COMMIT();
                }
            }

            // -------- epilogue (no barrier between this and next mainloop) --------
            int Itc, sc; decode_unit(p0 + t, Itc, sc);
            const int jb = ((Itc + sc) & (NTILES - 1)) * TILE;
            if (sc == 0)
                epi_diag(c, labels, jb, ibase, m0, n0, lane,
                         all_lo, all_hi, pos_lo, pos_hi);
            else
                epi_offdiag_h2(c, labels, jb, n0, lane,
                               rlo, rhi, all_lo, all_hi, pos_lo, pos_hi);

            // segment boundary: flush rows of It0, switch labels to It1
            if (tb < cnt && t == tb - 1) {
                flush_rows(ibase, m0, lane, all_lo, all_hi, pos_lo, pos_hi);
                ibase = It1 * TILE;
#pragma unroll
                for (int m = 0; m < 4; ++m) {
                    const int llo = __ldg(&labels[ibase + m0 + m * 16 + (lane >> 2)]);
                    const int lhi = __ldg(&labels[ibase + m0 + m * 16 + (lane >> 2) + 8]);
                    rlo[m] = __half2half2(__int2half_rn(llo));
                    rhi[m] = __half2half2(__int2half_rn(lhi));
                    all_lo[m] = 0.0f; all_hi[m] = 0.0f;
                    pos_lo[m] = 0.0f; pos_hi[m] = 0.0f;
                }
            }
        }
        flush_rows(ibase, m0, lane, all_lo, all_hi, pos_lo, pos_hi);
    }
    gsync(1);

    // ---------------- Phase 2: distributed loss reduction ----------------
    {
        float lsum = 0.0f; int lnv = 0, lnfg = 0;
        const int base = blockIdx.x * NR_PER_CTA;
        for (int i = tid; i < NR_PER_CTA; i += 256) {
            const int row = base + i;
            if (row < NROWS) {
                const int lab = labels[row];
                const bool fg = (lab >= 0);
                if (fg) lnfg++;
                const float pp = g_pos[row];
                const float aa = g_all[row];
                if (fg && pp > 0.0f) {
                    float pc = fminf(fmaxf(pp, 1e-6f), 1e6f);
                    float ac = fminf(fmaxf(aa, 1e-6f), 1e6f);
                    lsum += fminf(__logf(ac) - __logf(pc), 10.0f);
                    lnv++;
                }
            }
        }
#pragma unroll
        for (int o = 16; o > 0; o >>= 1) {
            lsum += __shfl_xor_sync(0xffffffffu, lsum, o);
            lnv  += __shfl_xor_sync(0xffffffffu, lnv, o);
            lnfg += __shfl_xor_sync(0xffffffffu, lnfg, o);
        }
        if (lane == 0) { s_rs[wid] = lsum; s_rv[wid] = lnv; s_rf[wid] = lnfg; }
        __syncthreads();
        if (tid == 0) {
            float ts = 0.0f; int tv = 0, tf = 0;
#pragma unroll
            for (int w = 0; w < 8; ++w) { ts += s_rs[w]; tv += s_rv[w]; tf += s_rf[w]; }
            if (ts != 0.0f || tv || tf) {
                atomicAdd(&g_rsum, ts);
                atomicAdd(&g_rnv, tv);
                atomicAdd(&g_rnfg, tf);
            }
            __threadfence();
            atomicAdd(&g_bar[2], 1u);     // arrival-only barrier
        }
    }

    // ---------------- Phase 3: CTA0 finalizes and resets state ----------------
    if (blockIdx.x == 0 && tid == 0) {
        while (*((volatile unsigned*)&g_bar[2]) < GRIDN) { }
        __threadfence();
        const float ts = g_rsum;
        const int   tv = g_rnv;
        const int   tf = g_rnfg;
        const float mean = ts / (float)(tv > 0 ? tv : 1);
        out[0] = (tf >= 2 && tv > 0) ? mean : 0.0f;
        // self-clean for the next launch (all CTAs are past every spin by now)
        g_bar[0] = 0u; g_bar[1] = 0u; g_bar[2] = 0u;
        g_rsum = 0.0f; g_rnv = 0; g_rnfg = 0;
    }
}

// ============================================================================
extern "C" void kernel_launch(void* const* d_in, const int* in_sizes, int n_in,
                              void* d_out, int out_size) {
    const float* features = (const float*)d_in[0];
    const int*   labels   = (const int*)d_in[1];
    float*       out      = (float*)d_out;

    cudaFuncSetAttribute(cpe_fused_kernel,
                         cudaFuncAttributeMaxDynamicSharedMemorySize, SM_TOTAL);

    cpe_fused_kernel<<<GRIDN, 256, SM_TOTAL>>>(features, labels, out);
}

// round 17
// speedup vs baseline: 1.0301x; 1.0301x over previous
#include <cuda_runtime.h>
#include <cuda_bf16.h>
#include <cuda_fp16.h>
#include <cstdint>

#define NROWS 8192
#define DIM   128
#define TILE  128
#define NTILES (NROWS / TILE)             // 64
#define NUNITS 2080
#define GRIDN  296
#define NR_PER_CTA 28                     // 296*28 = 8288 >= 8192

// sqrt(log2(e)/0.1) — baked into both operands so acc = sim*log2(e)/T
#define ROOT_SCALE 3.79828255588053f

// dynamic smem: A0 16K | A1 16K | B0 16K | B1 16K
#define SM_TOTAL 65536

__device__ uint8_t g_f8[NROWS * DIM];    // normalized * ROOT_SCALE, e4m3; bg rows zeroed
__device__ float g_pos[NROWS];
__device__ float g_all[NROWS];
__device__ unsigned g_bar[3];            // spin barriers (self-cleaning)
__device__ float g_rsum;
__device__ int   g_rnv;
__device__ int   g_rnfg;
__device__ int   g_nbg;                  // count of background rows

// ============================ PTX helpers ============================
__device__ __forceinline__ uint32_t smem_u32(const void* p) {
    uint32_t a;
    asm("{ .reg .u64 t; cvta.to.shared.u64 t, %1; cvt.u32.u64 %0, t; }"
        : "=r"(a) : "l"(p));
    return a;
}
__device__ __forceinline__ float fast_ex2(float x) {
    float r; asm("ex2.approx.f32 %0, %1;" : "=f"(r) : "f"(x)); return r;
}
#define CP_ASYNC16(dst, src) \
    asm volatile("cp.async.cg.shared.global [%0], [%1], 16;" \
                 :: "r"(dst), "l"(src) : "memory")
#define CP_COMMIT() asm volatile("cp.async.commit_group;" ::: "memory")
#define CP_WAIT0()  asm volatile("cp.async.wait_group 0;" ::: "memory")
#define CP_WAIT1()  asm volatile("cp.async.wait_group 1;" ::: "memory")

__device__ __forceinline__ void ldsm4(uint32_t* r, uint32_t addr) {
    asm volatile("ldmatrix.sync.aligned.m8n8.x4.shared.b16 {%0,%1,%2,%3}, [%4];"
                 : "=r"(r[0]), "=r"(r[1]), "=r"(r[2]), "=r"(r[3]) : "r"(addr));
}
// fp8 e4m3 MMA, K=32, f16 accumulate
__device__ __forceinline__ void mma16832h(uint32_t* d, const uint32_t* a,
                                          uint32_t b0, uint32_t b1) {
    asm volatile(
        "mma.sync.aligned.m16n8k32.row.col.f16.e4m3.e4m3.f16 "
        "{%0,%1}, {%2,%3,%4,%5}, {%6,%7}, {%0,%1};"
        : "+r"(d[0]), "+r"(d[1])
        : "r"(a[0]), "r"(a[1]), "r"(a[2]), "r"(a[3]), "r"(b0), "r"(b1));
}

// device-wide barrier: all 296 CTAs resident -> safe.
__device__ __forceinline__ void gsync(int i) {
    __syncthreads();
    if (threadIdx.x == 0) {
        __threadfence();
        atomicAdd(&g_bar[i], 1u);
        while (*((volatile unsigned*)&g_bar[i]) < GRIDN) { }
        __threadfence();
    }
    __syncthreads();
}

// Load a 128-row x 128-byte tile, k-group-major: addr = (g*128 + row)*16.
__device__ __forceinline__ void load_tile(uint32_t dst, int rowbase, int tid) {
#pragma unroll
    for (int it = 0; it < 4; ++it) {
        int id = it * 256 + tid;          // 0..1023
        int g = id >> 7, r = id & 127;
        const uint8_t* src = g_f8 + (size_t)(rowbase + r) * DIM + g * 16;
        CP_ASYNC16(dst + (uint32_t)id * 16u, src);
    }
}

// It-major flat enumeration: It<32 own s=0..32 (33 units), It>=32 own s=0..31.
__device__ __forceinline__ void decode_unit(int p, int& It, int& s) {
    if (p < 1056) { It = p / 33; s = p - It * 33; }
    else          { int q = p - 1056; It = 32 + (q >> 5); s = q & 31; }
}

__device__ __forceinline__ uint32_t pack_e4m3x4(float x0, float x1, float x2, float x3) {
    uint16_t p01, p23;
    asm("cvt.rn.satfinite.e4m3x2.f32 %0, %1, %2;" : "=h"(p01) : "f"(x1), "f"(x0));
    asm("cvt.rn.satfinite.e4m3x2.f32 %0, %1, %2;" : "=h"(p23) : "f"(x3), "f"(x2));
    return (uint32_t)p01 | ((uint32_t)p23 << 16);
}
__device__ __forceinline__ __half2 h2_of(uint32_t u) {
    return *reinterpret_cast<const __half2*>(&u);
}
__device__ __forceinline__ uint32_t u_of(__half2 h) {
    return *reinterpret_cast<const uint32_t*>(&h);
}

// ============================ epilogues ============================
// Diagonal tile: float path (64/2080 tiles only). Only self-exclusion needed;
// bg handling is via zeroed vectors + global n_bg correction.
__device__ __forceinline__ void epi_diag(
    const uint32_t c[4][4][2], const int* __restrict__ labels, int jb, int ibase,
    int m0, int n0, int lane,
    float* all_lo, float* all_hi, float* pos_lo, float* pos_hi)
{
    int li_lo[4], li_hi[4];
#pragma unroll
    for (int m = 0; m < 4; ++m) {
        li_lo[m] = __ldg(&labels[ibase + m0 + m * 16 + (lane >> 2)]);
        li_hi[m] = __ldg(&labels[ibase + m0 + m * 16 + (lane >> 2) + 8]);
    }
#pragma unroll
    for (int n = 0; n < 4; ++n) {
        const int cl  = n0 + n * 8 + (lane & 3) * 2;
        const int lj0 = __ldg(&labels[jb + cl]);
        const int lj1 = __ldg(&labels[jb + cl + 1]);
        const int j0  = jb + cl;
        const int j1  = j0 + 1;
#pragma unroll
        for (int m = 0; m < 4; ++m) {
            const int i_lo = ibase + m0 + m * 16 + (lane >> 2);
            const int i_hi = i_lo + 8;
            const float2 p01 = __half22float2(h2_of(c[m][n][0]));
            const float2 p23 = __half22float2(h2_of(c[m][n][1]));
            float e0 = fast_ex2(p01.x);
            float e1 = fast_ex2(p01.y);
            float e2 = fast_ex2(p23.x);
            float e3 = fast_ex2(p23.y);
            e0 = (j0 != i_lo) ? e0 : 0.0f;
            e1 = (j1 != i_lo) ? e1 : 0.0f;
            e2 = (j0 != i_hi) ? e2 : 0.0f;
            e3 = (j1 != i_hi) ? e3 : 0.0f;
            all_lo[m] += e0 + e1;
            all_hi[m] += e2 + e3;
            pos_lo[m] += ((lj0 == li_lo[m]) ? e0 : 0.0f) + ((lj1 == li_lo[m]) ? e1 : 0.0f);
            pos_hi[m] += ((lj0 == li_hi[m]) ? e2 : 0.0f) + ((lj1 == li_hi[m]) ? e3 : 0.0f);
        }
    }
}

// Off-diagonal tile: f16x2-SIMD, NO fg masks (bg rows are zero vectors; e=1
// contributions corrected globally by n_bg in phase 2).
__device__ __forceinline__ void epi_offdiag_h2(
    const uint32_t c[4][4][2], const int* __restrict__ labels, int jb,
    int n0, int lane,
    const __half2* rlo, const __half2* rhi,
    float* all_lo, float* all_hi, float* pos_lo, float* pos_hi)
{
    const __half2 hz = __float2half2_rn(0.0f);
    __half2 colh[4], hca[4], hcp[4];
#pragma unroll
    for (int n = 0; n < 4; ++n) {
        const int cl = n0 + n * 8 + (lane & 3) * 2;
        const int lj0 = __ldg(&labels[jb + cl]);
        const int lj1 = __ldg(&labels[jb + cl + 1]);
        colh[n] = __halves2half2(__int2half_rn(lj0), __int2half_rn(lj1));
        hca[n] = hz; hcp[n] = hz;
    }
#pragma unroll
    for (int m = 0; m < 4; ++m) {
        __half2 sal = hz, sah = hz, spl = hz, sph = hz;
#pragma unroll
        for (int n = 0; n < 4; ++n) {
            const __half2 e0 = h2exp2(h2_of(c[m][n][0]));   // row i_lo, 2 cols
            const __half2 e1 = h2exp2(h2_of(c[m][n][1]));   // row i_hi, 2 cols
            const __half2 eq0 = __heq2(colh[n], rlo[m]);    // fg-fg same label only
            const __half2 eq1 = __heq2(colh[n], rhi[m]);
            const __half2 pe0 = __hmul2(e0, eq0);
            const __half2 pe1 = __hmul2(e1, eq1);
            sal = __hadd2(sal, e0);                         // row all (unmasked)
            sah = __hadd2(sah, e1);
            spl = __hadd2(spl, pe0);                        // row pos
            sph = __hadd2(sph, pe1);
            hca[n] = __hadd2(hca[n], __hadd2(e0, e1));      // col all (unmasked)
            hcp[n] = __hadd2(hcp[n], __hadd2(pe0, pe1));    // col pos
        }
        float2 f;
        f = __half22float2(sal); all_lo[m] += f.x + f.y;
        f = __half22float2(sah); all_hi[m] += f.x + f.y;
        f = __half22float2(spl); pos_lo[m] += f.x + f.y;
        f = __half22float2(sph); pos_hi[m] += f.x + f.y;
    }
    // column partials: reduce in PACKED half2 across the 8 lanes sharing each column
#pragma unroll
    for (int n = 0; n < 4; ++n) {
        uint32_t ua = u_of(hca[n]);
        uint32_t up = u_of(hcp[n]);
#pragma unroll
        for (int o = 4; o <= 16; o <<= 1) {
            ua = u_of(__hadd2(h2_of(ua), h2_of(__shfl_xor_sync(0xffffffffu, ua, o))));
            up = u_of(__hadd2(h2_of(up), h2_of(__shfl_xor_sync(0xffffffffu, up, o))));
        }
        hca[n] = h2_of(ua);
        hcp[n] = h2_of(up);
    }
    if (lane < 4) {
#pragma unroll
        for (int n = 0; n < 4; ++n) {
            const int j0 = jb + n0 + n * 8 + lane * 2;
            const float2 a = __half22float2(hca[n]);
            const float2 p = __half22float2(hcp[n]);
            atomicAdd(&g_all[j0],     a.x);
            atomicAdd(&g_pos[j0],     p.x);
            atomicAdd(&g_all[j0 + 1], a.y);
            atomicAdd(&g_pos[j0 + 1], p.y);
        }
    }
}

__device__ __forceinline__ void flush_rows(
    int ibase, int m0, int lane,
    float* all_lo, float* all_hi, float* pos_lo, float* pos_hi)
{
#pragma unroll
    for (int m = 0; m < 4; ++m) {
#pragma unroll
        for (int o = 1; o <= 2; o <<= 1) {
            all_lo[m] += __shfl_xor_sync(0xffffffffu, all_lo[m], o);
            all_hi[m] += __shfl_xor_sync(0xffffffffu, all_hi[m], o);
            pos_lo[m] += __shfl_xor_sync(0xffffffffu, pos_lo[m], o);
            pos_hi[m] += __shfl_xor_sync(0xffffffffu, pos_hi[m], o);
        }
    }
    if ((lane & 3) == 0) {
#pragma unroll
        for (int m = 0; m < 4; ++m) {
            const int rr = ibase + m0 + m * 16 + (lane >> 2);
            atomicAdd(&g_all[rr],     all_lo[m]);
            atomicAdd(&g_pos[rr],     pos_lo[m]);
            atomicAdd(&g_all[rr + 8], all_hi[m]);
            atomicAdd(&g_pos[rr + 8], pos_hi[m]);
        }
    }
}

// ============================ Fused persistent kernel ============================
__global__ __launch_bounds__(256, 2) void cpe_fused_kernel(
    const float* __restrict__ feat, const int* __restrict__ labels,
    float* __restrict__ out)
{
    extern __shared__ char smem[];
    const uint32_t sb = smem_u32(smem);
    __shared__ float s_rs[8];
    __shared__ int   s_rv[8], s_rf[8];

    const int tid  = threadIdx.x;
    const int lane = tid & 31;
    const int wid  = tid >> 5;

    // ---------------- Phase 0: normalize -> e4m3 (bg rows zeroed), count bg ----------------
    {
        const int base = blockIdx.x * NR_PER_CTA;   // 28 rows = 14 pairs
        for (int pi = wid; pi < NR_PER_CTA / 2; pi += 8) {
            const int row0 = base + 2 * pi;
            if (row0 < NROWS) {
                const int lab0 = __ldg(&labels[row0]);
                const int lab1 = __ldg(&labels[row0 + 1]);
                float4 v0 = ((const float4*)(feat + (size_t)row0 * DIM))[lane];
                float4 v1 = ((const float4*)(feat + (size_t)(row0 + 1) * DIM))[lane];
                float s0 = v0.x * v0.x + v0.y * v0.y + v0.z * v0.z + v0.w * v0.w;
                float s1 = v1.x * v1.x + v1.y * v1.y + v1.z * v1.z + v1.w * v1.w;
#pragma unroll
                for (int o = 16; o > 0; o >>= 1) {
                    s0 += __shfl_xor_sync(0xffffffffu, s0, o);
                    s1 += __shfl_xor_sync(0xffffffffu, s1, o);
                }
                float i0 = rsqrtf(fmaxf(s0, 1e-24f)) * ROOT_SCALE;
                float i1 = rsqrtf(fmaxf(s1, 1e-24f)) * ROOT_SCALE;
                uint32_t w0 = (lab0 < 0) ? 0u
                    : pack_e4m3x4(v0.x * i0, v0.y * i0, v0.z * i0, v0.w * i0);
                uint32_t w1 = (lab1 < 0) ? 0u
                    : pack_e4m3x4(v1.x * i1, v1.y * i1, v1.z * i1, v1.w * i1);
                ((uint32_t*)(g_f8 + (size_t)row0 * DIM))[lane] = w0;
                ((uint32_t*)(g_f8 + (size_t)(row0 + 1) * DIM))[lane] = w1;
                if (lane == 0) {
                    g_pos[row0] = 0.0f; g_all[row0] = 0.0f;
                    g_pos[row0 + 1] = 0.0f; g_all[row0 + 1] = 0.0f;
                    const int nb = (lab0 < 0) + (lab1 < 0);
                    if (nb) atomicAdd(&g_nbg, nb);
                }
            }
        }
    }
    gsync(0);

    // ---------------- Phase 1: symmetric FP8 GEMM + fused exp-sum epilogue ----------------
    {
        const int m0 = (wid >> 2) * 64;
        const int n0 = (wid & 3) * 32;

        const int matid = lane >> 3, r = lane & 7;
        uint32_t a_off[4];
#pragma unroll
        for (int m = 0; m < 4; ++m)
            a_off[m] = (uint32_t)((matid >> 1) * 2048 +
                       (m0 + m * 16 + ((matid & 1) << 3) + r) * 16);
        const uint32_t b_off0 = (uint32_t)((matid & 1) * 2048 + (n0 +      ((matid >> 1) << 3) + r) * 16);
        const uint32_t b_off1 = (uint32_t)((matid & 1) * 2048 + (n0 + 16 + ((matid >> 1) << 3) + r) * 16);

        // contiguous chunk of the flat unit list: 2080 = 8*8 + 288*7
        const int b = blockIdx.x;
        const int p0  = b * 7 + min(b, 8);
        const int cnt = 7 + (b < 8 ? 1 : 0);

        int It0, s0;
        decode_unit(p0, It0, s0);
        // end of It0's segment in the flat enumeration
        const int segend = (It0 < 32) ? (It0 + 1) * 33 : 1056 + (It0 - 31) * 32;
        const int tb  = min(cnt, segend - p0);   // units in first segment
        const int It1 = It0 + 1;                 // second segment (if tb < cnt)

        // initial loads: group1 = A0 (+A1) + B(0);  group2 = B(1)
        load_tile(sb, It0 * TILE, tid);
        if (tb < cnt) load_tile(sb + 16384u, It1 * TILE, tid);
        load_tile(sb + 32768u, ((It0 + s0) & (NTILES - 1)) * TILE, tid);
        CP_COMMIT();
        {
            int Itt, st; decode_unit(p0 + 1, Itt, st);
            load_tile(sb + 49152u, ((Itt + st) & (NTILES - 1)) * TILE, tid);
        }
        CP_COMMIT();

        // row labels for first segment
        int ibase = It0 * TILE;
        __half2 rlo[4], rhi[4];
#pragma unroll
        for (int m = 0; m < 4; ++m) {
            const int llo = __ldg(&labels[ibase + m0 + m * 16 + (lane >> 2)]);
            const int lhi = __ldg(&labels[ibase + m0 + m * 16 + (lane >> 2) + 8]);
            rlo[m] = __half2half2(__int2half_rn(llo));
            rhi[m] = __half2half2(__int2half_rn(lhi));
        }
        float all_lo[4] = {0,0,0,0}, all_hi[4] = {0,0,0,0};
        float pos_lo[4] = {0,0,0,0}, pos_hi[4] = {0,0,0,0};

        CP_WAIT1();            // group1 (A tiles + B0) complete; B1 may be in flight
        __syncthreads();

        for (int t = 0; t < cnt; ++t) {
            const uint32_t SA = sb + ((t < tb) ? 0u : 16384u);
            const uint32_t SB = sb + 32768u + (uint32_t)(t & 1) * 16384u;

            // -------- mainloop: 16 fp8 MMAs x 4 k-steps --------
            uint32_t c[4][4][2];
#pragma unroll
            for (int m = 0; m < 4; ++m)
#pragma unroll
                for (int n = 0; n < 4; ++n) { c[m][n][0] = 0u; c[m][n][1] = 0u; }

#pragma unroll
            for (int ks = 0; ks < 4; ++ks) {
                const uint32_t kadv = (uint32_t)ks * 4096u;
                uint32_t af[4][4];
#pragma unroll
                for (int m = 0; m < 4; ++m) ldsm4(af[m], SA + a_off[m] + kadv);
                uint32_t bf0[4], bf1[4];
                ldsm4(bf0, SB + b_off0 + kadv);
                ldsm4(bf1, SB + b_off1 + kadv);
#pragma unroll
                for (int m = 0; m < 4; ++m) {
                    mma16832h(c[m][0], af[m], bf0[0], bf0[1]);
                    mma16832h(c[m][1], af[m], bf0[2], bf0[3]);
                    mma16832h(c[m][2], af[m], bf1[0], bf1[1]);
                    mma16832h(c[m][3], af[m], bf1[2], bf1[3]);
                }
            }

            // -------- barrier right after uniform mainloop; then prefetch t+2 --------
            if (t + 1 < cnt) {
                CP_WAIT0();          // B(t+1) data arrived (only group outstanding)
                __syncthreads();     // all warps done reading SB -> safe to overwrite
                if (t + 2 < cnt) {
                    int It2, s2; decode_unit(p0 + t + 2, It2, s2);
                    load_tile(SB, ((It2 + s2) & (NTILES - 1)) * TILE, tid);
                    CP_COMMIT();
                }
            }

            // -------- epilogue (no barrier between this and next mainloop) --------
            int Itc, sc; decode_unit(p0 + t, Itc, sc);
            const int jb = ((Itc + sc) & (NTILES - 1)) * TILE;
            if (sc == 0)
                epi_diag(c, labels, jb, ibase, m0, n0, lane,
                         all_lo, all_hi, pos_lo, pos_hi);
            else
                epi_offdiag_h2(c, labels, jb, n0, lane,
                               rlo, rhi, all_lo, all_hi, pos_lo, pos_hi);

            // segment boundary: flush rows of It0, switch labels to It1
            if (tb < cnt && t == tb - 1) {
                flush_rows(ibase, m0, lane, all_lo, all_hi, pos_lo, pos_hi);
                ibase = It1 * TILE;
#pragma unroll
                for (int m = 0; m < 4; ++m) {
                    const int llo = __ldg(&labels[ibase + m0 + m * 16 + (lane >> 2)]);
                    const int lhi = __ldg(&labels[ibase + m0 + m * 16 + (lane >> 2) + 8]);
                    rlo[m] = __half2half2(__int2half_rn(llo));
                    rhi[m] = __half2half2(__int2half_rn(lhi));
                    all_lo[m] = 0.0f; all_hi[m] = 0.0f;
                    pos_lo[m] = 0.0f; pos_hi[m] = 0.0f;
                }
            }
        }
        flush_rows(ibase, m0, lane, all_lo, all_hi, pos_lo, pos_hi);
    }
    gsync(1);

    // ---------------- Phase 2: distributed loss reduction (bg-corrected) ----------------
    {
        const float nbgf = (float)(*((volatile int*)&g_nbg));
        float lsum = 0.0f; int lnv = 0, lnfg = 0;
        const int base = blockIdx.x * NR_PER_CTA;
        for (int i = tid; i < NR_PER_CTA; i += 256) {
            const int row = base + i;
            if (row < NROWS) {
                const int lab = labels[row];
                const bool fg = (lab >= 0);
                if (fg) lnfg++;
                const float pp = g_pos[row];
                const float aa = g_all[row] - nbgf;   // remove e=1 bg contributions
                if (fg && pp > 0.0f) {
                    float pc = fminf(fmaxf(pp, 1e-6f), 1e6f);
                    float ac = fminf(fmaxf(aa, 1e-6f), 1e6f);
                    lsum += fminf(__logf(ac) - __logf(pc), 10.0f);
                    lnv++;
                }
            }
        }
#pragma unroll
        for (int o = 16; o > 0; o >>= 1) {
            lsum += __shfl_xor_sync(0xffffffffu, lsum, o);
            lnv  += __shfl_xor_sync(0xffffffffu, lnv, o);
            lnfg += __shfl_xor_sync(0xffffffffu, lnfg, o);
        }
        if (lane == 0) { s_rs[wid] = lsum; s_rv[wid] = lnv; s_rf[wid] = lnfg; }
        __syncthreads();
        if (tid == 0) {
            float ts = 0.0f; int tv = 0, tf = 0;
#pragma unroll
            for (int w = 0; w < 8; ++w) { ts += s_rs[w]; tv += s_rv[w]; tf += s_rf[w]; }
            if (ts != 0.0f || tv || tf) {
                atomicAdd(&g_rsum, ts);
                atomicAdd(&g_rnv, tv);
                atomicAdd(&g_rnfg, tf);
            }
            __threadfence();
            atomicAdd(&g_bar[2], 1u);     // arrival-only barrier
        }
    }

    // ---------------- Phase 3: CTA0 finalizes and resets state ----------------
    if (blockIdx.x == 0 && tid == 0) {
        while (*((volatile unsigned*)&g_bar[2]) < GRIDN) { }
        __threadfence();
        const float ts = g_rsum;
        const int   tv = g_rnv;
        const int   tf = g_rnfg;
        const float mean = ts / (float)(tv > 0 ? tv : 1);
        out[0] = (tf >= 2 && tv > 0) ? mean : 0.0f;
        // self-clean for the next launch (all CTAs are past every spin by now)
        g_bar[0] = 0u; g_bar[1] = 0u; g_bar[2] = 0u;
        g_rsum = 0.0f; g_rnv = 0; g_rnfg = 0; g_nbg = 0;
    }
}

// ============================================================================
extern "C" void kernel_launch(void* const* d_in, const int* in_sizes, int n_in,
                              void* d_out, int out_size) {
    const float* features = (const float*)d_in[0];
    const int*   labels   = (const int*)d_in[1];
    float*       out      = (float*)d_out;

    cudaFuncSetAttribute(cpe_fused_kernel,
                         cudaFuncAttributeMaxDynamicSharedMemorySize, SM_TOTAL);

    cpe_fused_kernel<<<GRIDN, 256, SM_TOTAL>>>(features, labels, out);
}